// round 13
// baseline (speedup 1.0000x reference)
#include <cuda_runtime.h>

#define BATCH    4
#define NPTS     4096
#define THREADS  256
#define QCHUNKS  (NPTS / THREADS)        // 16
#define GRID_T   (QCHUNKS * 2 * BATCH)   // 128 blocks
#define NBKT     1024
#define U0       (-12.0f)                // u = x+y+z ~ N(0,3); +-12 = 6.9 sigma
#define UW       (24.0f / NBKT)
#define INV_UW   (NBKT / 24.0f)

// spt: 4096 float4 (s=x+y, t=x-y, z, pad) in bucket order   65536 B
// off: 1025 u32 bucket start offsets                          4100 B
// cnt: 1024 u32 histogram / scatter cursors                   4096 B
// red: reduction scratch                                        64 B
#define SMEM_BYTES (4096 * 16 + 1025 * 4 + 1024 * 4 + 64)

__device__ float    g_acc;   // zero-init; last block resets after reading
__device__ unsigned g_cnt;

__global__ __launch_bounds__(THREADS)
void chamfer_bucket_kernel(const float* __restrict__ pred,
                           const float* __restrict__ gt,
                           float* __restrict__ out) {
    extern __shared__ char smem[];
    float4*   spt = reinterpret_cast<float4*>(smem);
    unsigned* off = reinterpret_cast<unsigned*>(smem + 4096 * 16);
    unsigned* cnt = off + 1025;
    float*    red = reinterpret_cast<float*>(cnt + 1024);
    unsigned* tkt = reinterpret_cast<unsigned*>(red + 9);

    const int tid    = threadIdx.x;
    const int qchunk = blockIdx.x;       // 0..15
    const int dir    = blockIdx.y;       // 0: pred->gt, 1: gt->pred
    const int b      = blockIdx.z;       // 0..3
    const int lane   = tid & 31;
    const int wid    = tid >> 5;

    const float* src = (dir ? gt : pred) + (size_t)b * NPTS * 3;  // queries
    const float* tgt = (dir ? pred : gt) + (size_t)b * NPTS * 3;  // targets

    // ---- Phase 1: bucket the target cloud by u = x+y+z ----
    for (int i = tid; i < NBKT; i += THREADS) cnt[i] = 0u;
    __syncthreads();

    #pragma unroll 4
    for (int k = 0; k < NPTS / THREADS; k++) {
        const int p = k * THREADS + tid;
        const float x = tgt[p * 3], y = tgt[p * 3 + 1], z = tgt[p * 3 + 2];
        int bk = (int)((x + y + z - U0) * INV_UW);
        bk = min(max(bk, 0), NBKT - 1);
        atomicAdd(&cnt[bk], 1u);
    }
    __syncthreads();

    // exclusive prefix over 1024 counters (4 per thread)
    {
        const unsigned c0 = cnt[tid * 4],     c1 = cnt[tid * 4 + 1];
        const unsigned c2 = cnt[tid * 4 + 2], c3 = cnt[tid * 4 + 3];
        const unsigned tsum = c0 + c1 + c2 + c3;
        unsigned scan = tsum;
        #pragma unroll
        for (int o = 1; o < 32; o <<= 1) {
            const unsigned n = __shfl_up_sync(0xffffffffu, scan, o);
            if (lane >= o) scan += n;
        }
        __shared__ unsigned wtot[8], wbase[8];
        if (lane == 31) wtot[wid] = scan;
        __syncthreads();
        if (tid < 8) {
            unsigned v = 0;
            for (int w = 0; w < 8; w++) { wbase[w] = (w == tid) ? v : wbase[w]; v += wtot[w]; }
        }
        // (serialize tiny 8-scan on thread 0 instead, race-free)
        __syncthreads();
        if (tid == 0) {
            unsigned v = 0;
            for (int w = 0; w < 8; w++) { wbase[w] = v; v += wtot[w]; }
        }
        __syncthreads();
        const unsigned base = wbase[wid] + scan - tsum;
        off[tid * 4]     = base;
        off[tid * 4 + 1] = base + c0;
        off[tid * 4 + 2] = base + c0 + c1;
        off[tid * 4 + 3] = base + c0 + c1 + c2;
        if (tid == THREADS - 1) off[NBKT] = NPTS;
    }
    __syncthreads();
    for (int i = tid; i < NBKT; i += THREADS) cnt[i] = off[i];  // scatter cursors
    __syncthreads();

    #pragma unroll 4
    for (int k = 0; k < NPTS / THREADS; k++) {
        const int p = k * THREADS + tid;
        const float x = tgt[p * 3], y = tgt[p * 3 + 1], z = tgt[p * 3 + 2];
        int bk = (int)((x + y + z - U0) * INV_UW);
        bk = min(max(bk, 0), NBKT - 1);
        const unsigned pos = atomicAdd(&cnt[bk], 1u);
        spt[pos] = make_float4(x + y, x - y, z, 0.0f);
    }
    __syncthreads();

    // ---- Phase 2: each thread resolves one query exactly ----
    const int qi = qchunk * THREADS + tid;
    const float qx = src[qi * 3], qy = src[qi * 3 + 1], qz = src[qi * 3 + 2];
    const float qs = qx + qy, qt = qx - qy;
    const float qu = qx + qy + qz;
    int bq = (int)((qu - U0) * INV_UW);
    bq = min(max(bq, 0), NBKT - 1);

    float cur = 3.4e38f;
    // scan a bucket: d = max(|dS|,|dT|) + |dz|  (== |dx|+|dy|+|dz|)
    #define SCAN_BKT(B)                                                   \
        do {                                                              \
            const unsigned e_ = off[(B) + 1];                             \
            for (unsigned i_ = off[(B)]; i_ < e_; i_++) {                 \
                const float4 f = spt[i_];                                 \
                const float d = fmaxf(fabsf(qs - f.x), fabsf(qt - f.y))   \
                              + fabsf(qz - f.z);                          \
                cur = fminf(cur, d);                                      \
            }                                                             \
        } while (0)

    SCAN_BKT(bq);
    {
        int bl = bq - 1, br = bq + 1;
        bool dl = (bl < 0), dr = (br > NBKT - 1);
        while (!dl || !dr) {
            if (!dl) {
                const float bound = qu - (U0 + (float)(bl + 1) * UW);
                if (bound < cur) { SCAN_BKT(bl); if (--bl < 0) dl = true; }
                else dl = true;
            }
            if (!dr) {
                const float bound = (U0 + (float)br * UW) - qu;
                if (bound < cur) { SCAN_BKT(br); if (++br > NBKT - 1) dr = true; }
                else dr = true;
            }
        }
    }
    #undef SCAN_BKT

    // ---- Phase 3: block sum -> global atomicAdd -> last block finalizes ----
    float sum = cur;
    #pragma unroll
    for (int o = 16; o; o >>= 1)
        sum += __shfl_xor_sync(0xffffffffu, sum, o);
    if (lane == 0) red[wid] = sum;
    __syncthreads();
    if (tid == 0) {
        float v = 0.0f;
        #pragma unroll
        for (int w = 0; w < 8; w++) v += red[w];
        atomicAdd(&g_acc, v);
        __threadfence();
        const unsigned ticket = atomicAdd(&g_cnt, 1u);
        *tkt = ticket;
        if (ticket == GRID_T - 1) {
            const float total = atomicAdd(&g_acc, 0.0f);   // coherent read
            out[0] = total * (1.0f / ((float)BATCH * (float)NPTS));
            __threadfence();
            g_acc = 0.0f;                                  // reset for replay
            g_cnt = 0u;
        }
    }
}

extern "C" void kernel_launch(void* const* d_in, const int* in_sizes, int n_in,
                              void* d_out, int out_size) {
    const float* pred = (const float*)d_in[0];
    const float* gt   = (const float*)d_in[1];
    float* out = (float*)d_out;
    (void)in_sizes; (void)n_in; (void)out_size;

    cudaFuncSetAttribute(chamfer_bucket_kernel,
                         cudaFuncAttributeMaxDynamicSharedMemorySize,
                         SMEM_BYTES);   // idempotent; first (uncaptured) call sets it

    dim3 grid(QCHUNKS, 2, BATCH);      // 16 x 2 x 4 = 128 blocks, one wave
    chamfer_bucket_kernel<<<grid, THREADS, SMEM_BYTES>>>(pred, gt, out);
}

// round 14
// speedup vs baseline: 2.1004x; 2.1004x over previous
#include <cuda_runtime.h>

#define BATCH    4
#define NPTS     4096
#define THREADS  256
#define QCHUNKS  (NPTS / THREADS)        // 16
#define GRID_T   (QCHUNKS * 2 * BATCH)   // 128 blocks
#define NBKT     1024
#define U0       (-12.0f)                // u = x+y+z ~ N(0,3); +-12 = 6.9 sigma
#define UW       (24.0f / NBKT)
#define INV_UW   (NBKT / 24.0f)

// sst: 4096 float2 (s=x+y, t=x-y) bucket-ordered   32768 B
// szs: 4096 float  (z)                              16384 B
// off: 1025 u32 bucket start offsets                 4100 B
// cnt: 1024 u32 histogram / scatter cursors          4096 B
// red: 8 floats                                        32 B
#define SMEM_BYTES (32768 + 16384 + 1025 * 4 + 1024 * 4 + 64)

__device__ float    g_acc;   // zero-init; last block resets after reading
__device__ unsigned g_cnt;

__global__ __launch_bounds__(THREADS)
void chamfer_bucket_kernel(const float* __restrict__ pred,
                           const float* __restrict__ gt,
                           float* __restrict__ out) {
    extern __shared__ char smem[];
    float2*   sst = reinterpret_cast<float2*>(smem);
    float*    szs = reinterpret_cast<float*>(smem + 32768);
    unsigned* off = reinterpret_cast<unsigned*>(smem + 32768 + 16384);
    unsigned* cnt = off + 1025;
    float*    red = reinterpret_cast<float*>(cnt + 1024);

    const int tid    = threadIdx.x;
    const int qchunk = blockIdx.x;       // 0..15
    const int dir    = blockIdx.y;       // 0: pred->gt, 1: gt->pred
    const int b      = blockIdx.z;       // 0..3
    const int lane   = tid & 31;
    const int wid    = tid >> 5;

    const float* src = (dir ? gt : pred) + (size_t)b * NPTS * 3;  // queries
    const float* tgt = (dir ? pred : gt) + (size_t)b * NPTS * 3;  // targets

    // ---- Phase 1: bucket the target cloud by u = x+y+z ----
    for (int i = tid; i < NBKT; i += THREADS) cnt[i] = 0u;
    __syncthreads();

    #pragma unroll 4
    for (int k = 0; k < NPTS / THREADS; k++) {
        const int p = k * THREADS + tid;
        const float x = tgt[p * 3], y = tgt[p * 3 + 1], z = tgt[p * 3 + 2];
        int bk = (int)((x + y + z - U0) * INV_UW);
        bk = min(max(bk, 0), NBKT - 1);
        atomicAdd(&cnt[bk], 1u);
    }
    __syncthreads();

    // exclusive prefix over 1024 counters (4 per thread)
    {
        __shared__ unsigned wtot[8], wbase[8];
        const unsigned c0 = cnt[tid * 4],     c1 = cnt[tid * 4 + 1];
        const unsigned c2 = cnt[tid * 4 + 2], c3 = cnt[tid * 4 + 3];
        const unsigned tsum = c0 + c1 + c2 + c3;
        unsigned scan = tsum;
        #pragma unroll
        for (int o = 1; o < 32; o <<= 1) {
            const unsigned n = __shfl_up_sync(0xffffffffu, scan, o);
            if (lane >= o) scan += n;
        }
        if (lane == 31) wtot[wid] = scan;
        __syncthreads();
        if (tid == 0) {
            unsigned v = 0;
            for (int w = 0; w < 8; w++) { wbase[w] = v; v += wtot[w]; }
        }
        __syncthreads();
        const unsigned base = wbase[wid] + scan - tsum;
        off[tid * 4]     = base;
        off[tid * 4 + 1] = base + c0;
        off[tid * 4 + 2] = base + c0 + c1;
        off[tid * 4 + 3] = base + c0 + c1 + c2;
        if (tid == THREADS - 1) off[NBKT] = NPTS;
    }
    __syncthreads();
    for (int i = tid; i < NBKT; i += THREADS) cnt[i] = off[i];  // scatter cursors
    __syncthreads();

    #pragma unroll 4
    for (int k = 0; k < NPTS / THREADS; k++) {
        const int p = k * THREADS + tid;
        const float x = tgt[p * 3], y = tgt[p * 3 + 1], z = tgt[p * 3 + 2];
        int bk = (int)((x + y + z - U0) * INV_UW);
        bk = min(max(bk, 0), NBKT - 1);
        const unsigned pos = atomicAdd(&cnt[bk], 1u);
        sst[pos] = make_float2(x + y, x - y);
        szs[pos] = z;
    }
    __syncthreads();

    // ---- Phase 2: warp-cooperative exact NN, one query at a time ----
    // Per-lane query (this thread's own), broadcast one per iteration.
    const int qi = qchunk * THREADS + tid;
    const float mx = src[qi * 3], my = src[qi * 3 + 1], mz = src[qi * 3 + 2];
    const float mqs = mx + my, mqt = mx - my, mqu = mx + my + mz;
    int mbq = (int)((mqu - U0) * INV_UW);
    mbq = min(max(mbq, 0), NBKT - 1);

    float qsum = 0.0f;   // lane 0 accumulates its warp's 32 query mins

    #pragma unroll 1
    for (int q = 0; q < 32; q++) {
        const float qs = __shfl_sync(0xffffffffu, mqs, q);
        const float qt = __shfl_sync(0xffffffffu, mqt, q);
        const float qz = __shfl_sync(0xffffffffu, mz,  q);
        const float qu = __shfl_sync(0xffffffffu, mqu, q);
        const int   bq = __shfl_sync(0xffffffffu, mbq, q);

        // Initial upper bound: 96 contiguous candidates around the bucket.
        int lo = (int)off[bq] - 48;
        lo = min(max(lo, 0), NPTS - 96);
        float cur = 3.4e38f;
        #pragma unroll
        for (int k = 0; k < 3; k++) {
            const int i = lo + k * 32 + lane;
            const float2 st = sst[i];
            const float d = fmaxf(fabsf(qs - st.x), fabsf(qt - st.y))
                          + fabsf(qz - szs[i]);
            cur = fminf(cur, d);
        }
        #pragma unroll
        for (int o = 16; o; o >>= 1)
            cur = fminf(cur, __shfl_xor_sync(0xffffffffu, cur, o));

        // Exact window: all candidates with |u - qu| <= cur (d >= |du|).
        int blo = (int)((qu - cur - U0) * INV_UW);
        int bhi = (int)((qu + cur - U0) * INV_UW);
        blo = min(max(blo, 0), NBKT - 1);
        bhi = min(max(bhi, 0), NBKT - 1);
        const unsigned wlo = off[blo], whi = off[bhi + 1];

        float best = cur;
        for (unsigned i = wlo + lane; i < whi; i += 32) {
            const float2 st = sst[i];
            const float d = fmaxf(fabsf(qs - st.x), fabsf(qt - st.y))
                          + fabsf(qz - szs[i]);
            best = fminf(best, d);
        }
        #pragma unroll
        for (int o = 16; o; o >>= 1)
            best = fminf(best, __shfl_xor_sync(0xffffffffu, best, o));

        if (lane == 0) qsum += best;
    }

    // ---- Phase 3: block sum -> global atomicAdd -> last block finalizes ----
    if (lane == 0) red[wid] = qsum;
    __syncthreads();
    if (tid == 0) {
        float v = 0.0f;
        #pragma unroll
        for (int w = 0; w < 8; w++) v += red[w];
        atomicAdd(&g_acc, v);
        __threadfence();
        const unsigned ticket = atomicAdd(&g_cnt, 1u);
        if (ticket == GRID_T - 1) {
            const float total = atomicAdd(&g_acc, 0.0f);   // coherent read
            out[0] = total * (1.0f / ((float)BATCH * (float)NPTS));
            __threadfence();
            g_acc = 0.0f;                                  // reset for replay
            g_cnt = 0u;
        }
    }
}

extern "C" void kernel_launch(void* const* d_in, const int* in_sizes, int n_in,
                              void* d_out, int out_size) {
    const float* pred = (const float*)d_in[0];
    const float* gt   = (const float*)d_in[1];
    float* out = (float*)d_out;
    (void)in_sizes; (void)n_in; (void)out_size;

    cudaFuncSetAttribute(chamfer_bucket_kernel,
                         cudaFuncAttributeMaxDynamicSharedMemorySize,
                         SMEM_BYTES);   // idempotent; set on uncaptured first call

    dim3 grid(QCHUNKS, 2, BATCH);      // 16 x 2 x 4 = 128 blocks, one wave
    chamfer_bucket_kernel<<<grid, THREADS, SMEM_BYTES>>>(pred, gt, out);
}